// round 6
// baseline (speedup 1.0000x reference)
#include <cuda_runtime.h>
#include <cuda_fp16.h>
#include <math.h>

#define BATCH 8
#define H 1024
#define W 1024
#define NWIN 5
#define PADY 64
#define ROWS (H + 2 * PADY)   // 1152 rows per (win,batch) image in scratch
#define NIMG (NWIN * BATCH)   // 40

__device__ __constant__ int c_radii[NWIN] = {3, 7, 15, 31, 63};
// y-chunk counts per window (chunk height = H / yc): more chunks for small r
// so priming overhead (2r rows per chunk) stays ~uniform (~20%).
__device__ __constant__ int c_yc[NWIN] = {32, 16, 8, 4, 2};
// exclusive prefix of blocks per window: blocks_w = yc_w * 2 xblk * BATCH
__device__ __constant__ int c_off[NWIN + 1] = {0, 512, 768, 896, 960, 992};
#define VGRID 992

// Scratch: horizontal window sums (sum x, sum x^2) packed as half2, with
// PADY zero rows above and below each image so the vertical pass needs no
// bounds checks. Pad rows are NEVER written; __device__ globals are
// zero-initialized at module load, so they remain zero deterministically.
__device__ __half2 g_hsums[(size_t)NIMG * ROWS * W];

// ---------------------------------------------------------------------------
// Pass A: per-row inclusive prefix of (x, x^2) via warp shuffles + one block
// combine, then emit the 5 horizontal clipped-window sums as half2.
// One block per (row, batch). 1024 threads.
// ---------------------------------------------------------------------------
__global__ __launch_bounds__(1024) void hpass_kernel(const float* __restrict__ x,
                                                     __half2* __restrict__ hsums) {
    const int y = blockIdx.x;
    const int b = blockIdx.y;
    const int t = threadIdx.x;
    const int lane = t & 31;
    const int wid = t >> 5;

    __shared__ float2 s_warp[32];
    __shared__ float2 s_pref[W];

    const float v = x[((size_t)b * H + y) * W + t];
    float sx = v, sy = v * v;

#pragma unroll
    for (int off = 1; off < 32; off <<= 1) {
        float ax = __shfl_up_sync(0xffffffffu, sx, off);
        float ay = __shfl_up_sync(0xffffffffu, sy, off);
        if (lane >= off) { sx += ax; sy += ay; }
    }
    if (lane == 31) s_warp[wid] = make_float2(sx, sy);
    __syncthreads();
    if (wid == 0) {
        float2 w2 = s_warp[lane];
        float wx = w2.x, wy = w2.y;
#pragma unroll
        for (int off = 1; off < 32; off <<= 1) {
            float ax = __shfl_up_sync(0xffffffffu, wx, off);
            float ay = __shfl_up_sync(0xffffffffu, wy, off);
            if (lane >= off) { wx += ax; wy += ay; }
        }
        s_warp[lane] = make_float2(wx, wy);
    }
    __syncthreads();
    if (wid > 0) {
        float2 base = s_warp[wid - 1];
        sx += base.x; sy += base.y;
    }
    s_pref[t] = make_float2(sx, sy);
    __syncthreads();

#pragma unroll
    for (int w = 0; w < NWIN; w++) {
        const int r = c_radii[w];
        const int lo = max(t - r, 0);
        const int hi = min(t + r, W - 1);
        float2 s = s_pref[hi];
        if (lo > 0) {
            float2 p = s_pref[lo - 1];
            s.x -= p.x; s.y -= p.y;
        }
        hsums[((size_t)(w * BATCH + b) * ROWS + PADY + y) * W + t] =
            __floats2half2_rn(s.x, s.y);
    }
}

// ---------------------------------------------------------------------------
// Pass B: vertical sliding window + Sauvola epilogue.
// Each thread owns 2 adjacent columns (8B uint2 loads). No conditionals in
// the loop (pad rows are zero). Flattened 1D grid with per-window y-chunk
// counts decoded from constant tables.
// ---------------------------------------------------------------------------
#define TPB 256

__global__ __launch_bounds__(TPB) void vpass_kernel(const __half2* __restrict__ hsums,
                                                    const float* __restrict__ kk,
                                                    const float* __restrict__ RR,
                                                    float* __restrict__ out) {
    const int idx = blockIdx.x;
    int w = 0;
#pragma unroll
    for (int i = 1; i < NWIN; i++)
        if (idx >= c_off[i]) w = i;
    const int rel = idx - c_off[w];
    const int yc = c_yc[w];
    const int per_b = yc * 2;            // 2 xblocks per chunk row
    const int b = rel / per_b;
    const int rr = rel - b * per_b;
    const int ychunk = rr >> 1;
    const int xblk = rr & 1;
    const int chunk = H / yc;

    const int tx = xblk * TPB + threadIdx.x;   // 0..511, uint2 index (2 cols)
    const int x0 = 2 * tx;
    const int x1 = x0 + 1;
    const int r = c_radii[w];
    const float kw = kk[w];
    const float invR = __frcp_rn(RR[w]);

    const uint2* col = reinterpret_cast<const uint2*>(
        hsums + ((size_t)(w * BATCH + b) * ROWS + PADY) * W) + tx;
    float* o = out + (((size_t)b * NWIN + w) * H) * W + x0;

    const float cnth0 = (float)(min(x0 + r, W - 1) - max(x0 - r, 0) + 1);
    const float cnth1 = (float)(min(x1 + r, W - 1) - max(x1 - r, 0) + 1);

    const int y0 = ychunk * chunk;

    float sx0 = 0.f, sy0 = 0.f, sx1 = 0.f, sy1 = 0.f;

    // Prime: S = sum of rows [y0-r, y0+r) (pad rows are zero, no clamping).
#pragma unroll 4
    for (int yy = y0 - r; yy < y0 + r; yy++) {
        uint2 u = col[(size_t)yy * (W / 2)];
        float2 f0 = __half22float2(*reinterpret_cast<__half2*>(&u.x));
        float2 f1 = __half22float2(*reinterpret_cast<__half2*>(&u.y));
        sx0 += f0.x; sy0 += f0.y; sx1 += f1.x; sy1 += f1.y;
    }

#pragma unroll 8
    for (int y = y0; y < y0 + chunk; y++) {
        {   // add row y+r
            uint2 u = col[(size_t)(y + r) * (W / 2)];
            float2 f0 = __half22float2(*reinterpret_cast<__half2*>(&u.x));
            float2 f1 = __half22float2(*reinterpret_cast<__half2*>(&u.y));
            sx0 += f0.x; sy0 += f0.y; sx1 += f1.x; sy1 += f1.y;
        }
        const float cntv = (float)(min(y + r, H - 1) - max(y - r, 0) + 1);
        {
            const float inv0 = __frcp_rn(cnth0 * cntv);
            const float inv1 = __frcp_rn(cnth1 * cntv);
            const float mean0 = sx0 * inv0, m20 = sy0 * inv0;
            const float mean1 = sx1 * inv1, m21 = sy1 * inv1;
            const float var0 = fmaxf(fmaf(-mean0, mean0, m20), 1e-6f);
            const float var1 = fmaxf(fmaf(-mean1, mean1, m21), 1e-6f);
            const float dev0 = var0 * __frsqrt_rn(var0);
            const float dev1 = var1 * __frsqrt_rn(var1);
            float2 res;
            res.x = mean0 * fmaf(kw, fmaf(dev0, invR, -1.0f), 1.0f);
            res.y = mean1 * fmaf(kw, fmaf(dev1, invR, -1.0f), 1.0f);
            *reinterpret_cast<float2*>(o + (size_t)y * W) = res;
        }
        {   // subtract row y-r (pads are zero -> harmless before y=r)
            uint2 u = col[(size_t)(y - r) * (W / 2)];
            float2 f0 = __half22float2(*reinterpret_cast<__half2*>(&u.x));
            float2 f1 = __half22float2(*reinterpret_cast<__half2*>(&u.y));
            sx0 -= f0.x; sy0 -= f0.y; sx1 -= f1.x; sy1 -= f1.y;
        }
    }
}

extern "C" void kernel_launch(void* const* d_in, const int* in_sizes, int n_in,
                              void* d_out, int out_size) {
    const float* x = (const float*)d_in[0];
    const float* k = (const float*)d_in[1];
    const float* R = (const float*)d_in[2];
    float* out = (float*)d_out;

    __half2* hsums;
    cudaGetSymbolAddress((void**)&hsums, g_hsums);

    dim3 gridA(H, BATCH);
    hpass_kernel<<<gridA, 1024>>>(x, hsums);

    vpass_kernel<<<VGRID, TPB>>>(hsums, k, R, out);
}

// round 7
// speedup vs baseline: 2.6972x; 2.6972x over previous
#include <cuda_runtime.h>
#include <cuda_fp16.h>
#include <math.h>

#define BATCH 8
#define H 1024
#define W 1024
#define NWIN 5
#define PADY 64
#define ROWS (H + 2 * PADY)   // 1152 rows per (win,batch) image in scratch
#define NIMG (NWIN * BATCH)   // 40

__device__ __constant__ int c_radii[NWIN] = {3, 7, 15, 31, 63};
// launch big windows first (z=0 -> w=4) so long blocks don't form a tail
__device__ __constant__ int c_worder[NWIN] = {4, 3, 2, 1, 0};

// Scratch: horizontal window sums (sum x, sum x^2) packed as half2, with
// PADY zero rows above and below each image so the vertical pass needs no
// bounds checks. Pad rows are NEVER written; __device__ globals are
// zero-initialized at module load, so they remain zero deterministically.
__device__ __half2 g_hsums[(size_t)NIMG * ROWS * W];

// ---------------------------------------------------------------------------
// Pass A: per-row inclusive prefix of (x, x^2) via warp shuffles + one block
// combine, then emit the 5 horizontal clipped-window sums as half2.
// One block per (row, batch). 1024 threads.
// ---------------------------------------------------------------------------
__global__ __launch_bounds__(1024) void hpass_kernel(const float* __restrict__ x,
                                                     __half2* __restrict__ hsums) {
    const int y = blockIdx.x;
    const int b = blockIdx.y;
    const int t = threadIdx.x;
    const int lane = t & 31;
    const int wid = t >> 5;

    __shared__ float2 s_warp[32];
    __shared__ float2 s_pref[W];

    const float v = x[((size_t)b * H + y) * W + t];
    float sx = v, sy = v * v;

#pragma unroll
    for (int off = 1; off < 32; off <<= 1) {
        float ax = __shfl_up_sync(0xffffffffu, sx, off);
        float ay = __shfl_up_sync(0xffffffffu, sy, off);
        if (lane >= off) { sx += ax; sy += ay; }
    }
    if (lane == 31) s_warp[wid] = make_float2(sx, sy);
    __syncthreads();
    if (wid == 0) {
        float2 w2 = s_warp[lane];
        float wx = w2.x, wy = w2.y;
#pragma unroll
        for (int off = 1; off < 32; off <<= 1) {
            float ax = __shfl_up_sync(0xffffffffu, wx, off);
            float ay = __shfl_up_sync(0xffffffffu, wy, off);
            if (lane >= off) { wx += ax; wy += ay; }
        }
        s_warp[lane] = make_float2(wx, wy);
    }
    __syncthreads();
    if (wid > 0) {
        float2 base = s_warp[wid - 1];
        sx += base.x; sy += base.y;
    }
    s_pref[t] = make_float2(sx, sy);
    __syncthreads();

#pragma unroll
    for (int w = 0; w < NWIN; w++) {
        const int r = c_radii[w];
        const int lo = max(t - r, 0);
        const int hi = min(t + r, W - 1);
        float2 s = s_pref[hi];
        if (lo > 0) {
            float2 p = s_pref[lo - 1];
            s.x -= p.x; s.y -= p.y;
        }
        hsums[((size_t)(w * BATCH + b) * ROWS + PADY + y) * W + t] =
            __floats2half2_rn(s.x, s.y);
    }
}

// ---------------------------------------------------------------------------
// Pass B: vertical sliding window + Sauvola epilogue.
// Each thread owns 2 adjacent columns (8B uint2 loads). No conditionals in
// the loop (pad rows are zero). Inner loop processes batches of BU rows:
// all 2*BU loads are issued into explicit register arrays first (high MLP),
// then the math runs. grid = (2*YCHUNKS, BATCH, NWIN) with z mapped so the
// largest window launches first.
// ---------------------------------------------------------------------------
#define TPB 256
#define XB2 (W / (2 * TPB))   // 2
#define YCHUNKS 8
#define YCHUNK (H / YCHUNKS)  // 128
#define BU 8                  // row batch (YCHUNK % BU == 0)

__global__ __launch_bounds__(TPB) void vpass_kernel(const __half2* __restrict__ hsums,
                                                    const float* __restrict__ kk,
                                                    const float* __restrict__ RR,
                                                    float* __restrict__ out) {
    const int xblk = blockIdx.x & (XB2 - 1);
    const int ychunk = blockIdx.x / XB2;
    const int b = blockIdx.y;
    const int w = c_worder[blockIdx.z];

    const int tx = xblk * TPB + threadIdx.x;   // uint2 index (2 cols)
    const int x0 = 2 * tx;
    const int x1 = x0 + 1;
    const int r = c_radii[w];
    const float kw = kk[w];
    const float invR = __frcp_rn(RR[w]);

    const uint2* col = reinterpret_cast<const uint2*>(
        hsums + ((size_t)(w * BATCH + b) * ROWS + PADY) * W) + tx;
    float* o = out + (((size_t)b * NWIN + w) * H) * W + x0;

    const float cnth0 = (float)(min(x0 + r, W - 1) - max(x0 - r, 0) + 1);
    const float cnth1 = (float)(min(x1 + r, W - 1) - max(x1 - r, 0) + 1);

    const int y0 = ychunk * YCHUNK;

    float sx0 = 0.f, sy0 = 0.f, sx1 = 0.f, sy1 = 0.f;

    // Prime: S = sum of rows [y0-r, y0+r) (pad rows are zero, no clamping).
#pragma unroll 4
    for (int yy = y0 - r; yy < y0 + r; yy++) {
        uint2 u = col[(size_t)yy * (W / 2)];
        float2 f0 = __half22float2(*reinterpret_cast<__half2*>(&u.x));
        float2 f1 = __half22float2(*reinterpret_cast<__half2*>(&u.y));
        sx0 += f0.x; sy0 += f0.y; sx1 += f1.x; sy1 += f1.y;
    }

    for (int yb = y0; yb < y0 + YCHUNK; yb += BU) {
        // ---- batch-load phase: 2*BU independent 8B loads ----
        uint2 ua[BU], us[BU];
#pragma unroll
        for (int j = 0; j < BU; j++) {
            ua[j] = col[(size_t)(yb + j + r) * (W / 2)];
            us[j] = col[(size_t)(yb + j - r) * (W / 2)];
        }
        // ---- math phase ----
#pragma unroll
        for (int j = 0; j < BU; j++) {
            const int y = yb + j;
            {
                float2 f0 = __half22float2(*reinterpret_cast<__half2*>(&ua[j].x));
                float2 f1 = __half22float2(*reinterpret_cast<__half2*>(&ua[j].y));
                sx0 += f0.x; sy0 += f0.y; sx1 += f1.x; sy1 += f1.y;
            }
            const float cntv = (float)(min(y + r, H - 1) - max(y - r, 0) + 1);
            const float inv0 = __frcp_rn(cnth0 * cntv);
            const float inv1 = __frcp_rn(cnth1 * cntv);
            const float mean0 = sx0 * inv0, m20 = sy0 * inv0;
            const float mean1 = sx1 * inv1, m21 = sy1 * inv1;
            const float var0 = fmaxf(fmaf(-mean0, mean0, m20), 1e-6f);
            const float var1 = fmaxf(fmaf(-mean1, mean1, m21), 1e-6f);
            const float dev0 = sqrtf(var0);
            const float dev1 = sqrtf(var1);
            float2 res;
            res.x = mean0 * fmaf(kw, fmaf(dev0, invR, -1.0f), 1.0f);
            res.y = mean1 * fmaf(kw, fmaf(dev1, invR, -1.0f), 1.0f);
            *reinterpret_cast<float2*>(o + (size_t)y * W) = res;
            {
                float2 f0 = __half22float2(*reinterpret_cast<__half2*>(&us[j].x));
                float2 f1 = __half22float2(*reinterpret_cast<__half2*>(&us[j].y));
                sx0 -= f0.x; sy0 -= f0.y; sx1 -= f1.x; sy1 -= f1.y;
            }
        }
    }
}

extern "C" void kernel_launch(void* const* d_in, const int* in_sizes, int n_in,
                              void* d_out, int out_size) {
    const float* x = (const float*)d_in[0];
    const float* k = (const float*)d_in[1];
    const float* R = (const float*)d_in[2];
    float* out = (float*)d_out;

    __half2* hsums;
    cudaGetSymbolAddress((void**)&hsums, g_hsums);

    dim3 gridA(H, BATCH);
    hpass_kernel<<<gridA, 1024>>>(x, hsums);

    dim3 gridB(XB2 * YCHUNKS, BATCH, NWIN);
    vpass_kernel<<<gridB, TPB>>>(hsums, k, R, out);
}

// round 8
// speedup vs baseline: 3.7139x; 1.3769x over previous
#include <cuda_runtime.h>
#include <cuda_fp16.h>
#include <math.h>

#define BATCH 8
#define H 1024
#define W 1024
#define NWIN 5
#define PADY 64
#define ROWS (H + 2 * PADY)   // 1152 rows per (win,batch) image in scratch
#define NIMG (NWIN * BATCH)   // 40

__device__ __constant__ int c_radii[NWIN] = {3, 7, 15, 31, 63};
// launch big windows first (z=0 -> w=4) so long blocks don't form a tail
__device__ __constant__ int c_worder[NWIN] = {4, 3, 2, 1, 0};

// Scratch: horizontal window sums (sum x, sum x^2) packed as half2, with
// PADY zero rows above and below each image so the vertical pass needs no
// bounds checks. Pad rows are NEVER written; __device__ globals are
// zero-initialized at module load, so they remain zero deterministically.
__device__ __half2 g_hsums[(size_t)NIMG * ROWS * W];

// ---------------------------------------------------------------------------
// Pass A: 256 threads, 4 consecutive pixels/thread. float4 load, per-thread
// serial prefix + warp scan + block combine. Prefix lives in smem padded
// every 16 entries (stride-4 float2 reads become conflict-free). Each window
// emits 4 half2 pixels as one uint4 store.
// One block per (row, batch).
// ---------------------------------------------------------------------------
#define HPB 256
#define PIDX(e) ((e) + ((e) >> 4))

__global__ __launch_bounds__(HPB) void hpass_kernel(const float* __restrict__ x,
                                                    uint4* __restrict__ hsums) {
    const int y = blockIdx.x;
    const int b = blockIdx.y;
    const int t = threadIdx.x;
    const int lane = t & 31;
    const int wid = t >> 5;

    __shared__ float2 s_warp[8];
    __shared__ float2 s_pref[PIDX(W - 1) + 1];   // padded

    const float4 v4 = reinterpret_cast<const float4*>(
        x + ((size_t)b * H + y) * W)[t];

    // per-thread serial inclusive prefix (4 px, 2 channels)
    float px0 = v4.x,        py0 = v4.x * v4.x;
    float px1 = px0 + v4.y,  py1 = py0 + v4.y * v4.y;
    float px2 = px1 + v4.z,  py2 = py1 + v4.z * v4.z;
    float px3 = px2 + v4.w,  py3 = py2 + v4.w * v4.w;

    // warp inclusive scan of thread totals
    float tx = px3, ty = py3;
#pragma unroll
    for (int off = 1; off < 32; off <<= 1) {
        float ax = __shfl_up_sync(0xffffffffu, tx, off);
        float ay = __shfl_up_sync(0xffffffffu, ty, off);
        if (lane >= off) { tx += ax; ty += ay; }
    }
    if (lane == 31) s_warp[wid] = make_float2(tx, ty);
    __syncthreads();
    if (wid == 0 && lane < 8) {
        float2 w2 = s_warp[lane];
        float wx = w2.x, wy = w2.y;
#pragma unroll
        for (int off = 1; off < 8; off <<= 1) {
            float ax = __shfl_up_sync(0xffu, wx, off);
            float ay = __shfl_up_sync(0xffu, wy, off);
            if (lane >= off) { wx += ax; wy += ay; }
        }
        s_warp[lane] = make_float2(wx, wy);
    }
    __syncthreads();

    float bx = tx - px3, by = ty - py3;        // thread-exclusive within warp
    if (wid > 0) {
        float2 wb = s_warp[wid - 1];
        bx += wb.x; by += wb.y;
    }

    const int q0 = 4 * t;
    s_pref[PIDX(q0 + 0)] = make_float2(bx + px0, by + py0);
    s_pref[PIDX(q0 + 1)] = make_float2(bx + px1, by + py1);
    s_pref[PIDX(q0 + 2)] = make_float2(bx + px2, by + py2);
    s_pref[PIDX(q0 + 3)] = make_float2(bx + px3, by + py3);
    __syncthreads();

#pragma unroll
    for (int w = 0; w < NWIN; w++) {
        const int r = c_radii[w];
        unsigned int h[4];
#pragma unroll
        for (int i = 0; i < 4; i++) {
            const int q = q0 + i;
            const int hi = min(q + r, W - 1);
            float2 s = s_pref[PIDX(hi)];
            if (q > r) {
                float2 p = s_pref[PIDX(q - r - 1)];
                s.x -= p.x; s.y -= p.y;
            }
            __half2 hh = __floats2half2_rn(s.x, s.y);
            h[i] = *reinterpret_cast<unsigned int*>(&hh);
        }
        uint4 pack = make_uint4(h[0], h[1], h[2], h[3]);
        hsums[((size_t)(w * BATCH + b) * ROWS + PADY + y) * (W / 4) + t] = pack;
    }
}

// ---------------------------------------------------------------------------
// Pass B: vertical sliding window + Sauvola epilogue.
// Each thread owns 2 adjacent columns (8B uint2 loads). No conditionals in
// the loop (pad rows are zero). Inner loop processes batches of BU rows:
// all 2*BU loads are issued into register arrays first (high MLP), then the
// math runs. TPB=128 / 16 y-chunks -> 2560 blocks for occupancy.
// ---------------------------------------------------------------------------
#define TPB 128
#define XB4 (W / (2 * TPB))   // 4
#define YCHUNKS 16
#define YCHUNK (H / YCHUNKS)  // 64
#define BU 8                  // row batch (YCHUNK % BU == 0)

__global__ __launch_bounds__(TPB) void vpass_kernel(const __half2* __restrict__ hsums,
                                                    const float* __restrict__ kk,
                                                    const float* __restrict__ RR,
                                                    float* __restrict__ out) {
    const int xblk = blockIdx.x & (XB4 - 1);
    const int ychunk = blockIdx.x / XB4;
    const int b = blockIdx.y;
    const int w = c_worder[blockIdx.z];

    const int tx = xblk * TPB + threadIdx.x;   // uint2 index (2 cols)
    const int x0 = 2 * tx;
    const int x1 = x0 + 1;
    const int r = c_radii[w];
    const float kw = kk[w];
    const float invR = __frcp_rn(RR[w]);

    const uint2* col = reinterpret_cast<const uint2*>(
        hsums + ((size_t)(w * BATCH + b) * ROWS + PADY) * W) + tx;
    float* o = out + (((size_t)b * NWIN + w) * H) * W + x0;

    const float cnth0 = (float)(min(x0 + r, W - 1) - max(x0 - r, 0) + 1);
    const float cnth1 = (float)(min(x1 + r, W - 1) - max(x1 - r, 0) + 1);

    const int y0 = ychunk * YCHUNK;

    float sx0 = 0.f, sy0 = 0.f, sx1 = 0.f, sy1 = 0.f;

    // Prime: S = sum of rows [y0-r, y0+r) (pad rows are zero, no clamping).
#pragma unroll 4
    for (int yy = y0 - r; yy < y0 + r; yy++) {
        uint2 u = col[(size_t)yy * (W / 2)];
        float2 f0 = __half22float2(*reinterpret_cast<__half2*>(&u.x));
        float2 f1 = __half22float2(*reinterpret_cast<__half2*>(&u.y));
        sx0 += f0.x; sy0 += f0.y; sx1 += f1.x; sy1 += f1.y;
    }

    for (int yb = y0; yb < y0 + YCHUNK; yb += BU) {
        // ---- batch-load phase: 2*BU independent 8B loads ----
        uint2 ua[BU], us[BU];
#pragma unroll
        for (int j = 0; j < BU; j++) {
            ua[j] = col[(size_t)(yb + j + r) * (W / 2)];
            us[j] = col[(size_t)(yb + j - r) * (W / 2)];
        }
        // ---- math phase ----
#pragma unroll
        for (int j = 0; j < BU; j++) {
            const int y = yb + j;
            {
                float2 f0 = __half22float2(*reinterpret_cast<__half2*>(&ua[j].x));
                float2 f1 = __half22float2(*reinterpret_cast<__half2*>(&ua[j].y));
                sx0 += f0.x; sy0 += f0.y; sx1 += f1.x; sy1 += f1.y;
            }
            const float cntv = (float)(min(y + r, H - 1) - max(y - r, 0) + 1);
            const float inv0 = __frcp_rn(cnth0 * cntv);
            const float inv1 = __frcp_rn(cnth1 * cntv);
            const float mean0 = sx0 * inv0, m20 = sy0 * inv0;
            const float mean1 = sx1 * inv1, m21 = sy1 * inv1;
            const float var0 = fmaxf(fmaf(-mean0, mean0, m20), 1e-6f);
            const float var1 = fmaxf(fmaf(-mean1, mean1, m21), 1e-6f);
            const float dev0 = sqrtf(var0);
            const float dev1 = sqrtf(var1);
            float2 res;
            res.x = mean0 * fmaf(kw, fmaf(dev0, invR, -1.0f), 1.0f);
            res.y = mean1 * fmaf(kw, fmaf(dev1, invR, -1.0f), 1.0f);
            *reinterpret_cast<float2*>(o + (size_t)y * W) = res;
            {
                float2 f0 = __half22float2(*reinterpret_cast<__half2*>(&us[j].x));
                float2 f1 = __half22float2(*reinterpret_cast<__half2*>(&us[j].y));
                sx0 -= f0.x; sy0 -= f0.y; sx1 -= f1.x; sy1 -= f1.y;
            }
        }
    }
}

extern "C" void kernel_launch(void* const* d_in, const int* in_sizes, int n_in,
                              void* d_out, int out_size) {
    const float* x = (const float*)d_in[0];
    const float* k = (const float*)d_in[1];
    const float* R = (const float*)d_in[2];
    float* out = (float*)d_out;

    __half2* hsums;
    cudaGetSymbolAddress((void**)&hsums, g_hsums);

    dim3 gridA(H, BATCH);
    hpass_kernel<<<gridA, HPB>>>(x, reinterpret_cast<uint4*>(hsums));

    dim3 gridB(XB4 * YCHUNKS, BATCH, NWIN);
    vpass_kernel<<<gridB, TPB>>>(hsums, k, R, out);
}